// round 1
// baseline (speedup 1.0000x reference)
#include <cuda_runtime.h>
#include <math.h>

#define L_SEQ 1024
#define H_DIM 2048
#define DI    4096
#define DT_R  128
#define NS    16
#define KC    4
#define FF    8192

// ---------------- scratch (static device globals; no allocation) ----------------
__device__ float g_xn   [L_SEQ * H_DIM];      // rmsnorm(hidden)
__device__ float g_proj [L_SEQ * 2 * DI];     // in_proj output (h | gate)
__device__ float g_h    [L_SEQ * DI];         // conv+silu output
__device__ float g_ssm  [L_SEQ * 160];        // x_proj output
__device__ float g_dtn  [L_SEQ * DT_R];
__device__ float g_Bn   [L_SEQ * NS];
__device__ float g_Cn   [L_SEQ * NS];
__device__ float g_delta[L_SEQ * DI];
__device__ float g_y    [L_SEQ * DI];
__device__ float g_res2 [L_SEQ * H_DIM];      // residual after mixer
__device__ float g_xn2  [L_SEQ * H_DIM];
__device__ float g_gu   [L_SEQ * 2 * FF];
__device__ float g_act  [L_SEQ * FF];

// ---------------- helpers ----------------
__device__ __forceinline__ float silu_f(float x) {
    return x / (1.f + __expf(-x));
}

// ---------------- rmsnorm (one block per row) ----------------
__global__ void __launch_bounds__(256) rmsnorm_kernel(
    const float* __restrict__ x, const float* __restrict__ w,
    float* __restrict__ out, int D)
{
    int row = blockIdx.x;
    const float* xr = x + (size_t)row * D;
    float s = 0.f;
    for (int i = threadIdx.x; i < D; i += 256) {
        float v = xr[i];
        s += v * v;
    }
    // block reduce
    __shared__ float red[8];
    #pragma unroll
    for (int o = 16; o >= 1; o >>= 1) s += __shfl_xor_sync(0xffffffffu, s, o);
    int warp = threadIdx.x >> 5;
    if ((threadIdx.x & 31) == 0) red[warp] = s;
    __syncthreads();
    if (warp == 0) {
        float t = ((threadIdx.x & 31) < 8) ? red[threadIdx.x & 31] : 0.f;
        #pragma unroll
        for (int o = 4; o >= 1; o >>= 1) t += __shfl_xor_sync(0xffffffffu, t, o);
        if (threadIdx.x == 0) red[0] = t;
    }
    __syncthreads();
    float r = rsqrtf(red[0] / (float)D + 1e-6f);
    float* orow = out + (size_t)row * D;
    for (int i = threadIdx.x; i < D; i += 256) {
        orow[i] = xr[i] * r * w[i];
    }
}

// ---------------- GEMM C[M,N] = A[M,K] @ B[N,K]^T (+ epilogue) ----------------
// EPI 0: plain store    EPI 1: +bias[n], softplus    EPI 2: +extra[m*N+n] (residual add)
template <int EPI>
__global__ void __launch_bounds__(256) gemm_abt(
    const float* __restrict__ A, const float* __restrict__ B,
    float* __restrict__ C, int M, int N, int K,
    const float* __restrict__ extra)
{
    const int BM = 128, BN = 128, BK = 8;
    __shared__ __align__(16) float As[BK][BM + 4];
    __shared__ __align__(16) float Bs[BK][BN + 4];

    int bm = blockIdx.y * BM;
    int bn = blockIdx.x * BN;
    int tid = threadIdx.x;
    int tx = tid & 15;       // 0..15
    int ty = tid >> 4;       // 0..15

    int lr = tid >> 1;        // 0..127 (tile row for loads)
    int lk = (tid & 1) * 4;   // 0 or 4

    float acc[8][8];
    #pragma unroll
    for (int i = 0; i < 8; i++)
        #pragma unroll
        for (int j = 0; j < 8; j++) acc[i][j] = 0.f;

    const float* Aptr = A + (size_t)(bm + lr) * K + lk;
    bool bvalid = (bn + lr) < N;
    const float* Bptr = B + (size_t)(bn + lr) * K + lk;

    for (int kt = 0; kt < K; kt += BK) {
        float4 av = *(const float4*)(Aptr + kt);
        float4 bv = bvalid ? *(const float4*)(Bptr + kt) : make_float4(0.f, 0.f, 0.f, 0.f);
        As[lk + 0][lr] = av.x; As[lk + 1][lr] = av.y;
        As[lk + 2][lr] = av.z; As[lk + 3][lr] = av.w;
        Bs[lk + 0][lr] = bv.x; Bs[lk + 1][lr] = bv.y;
        Bs[lk + 2][lr] = bv.z; Bs[lk + 3][lr] = bv.w;
        __syncthreads();
        #pragma unroll
        for (int k = 0; k < BK; k++) {
            float4 a0 = *(const float4*)(&As[k][ty * 8]);
            float4 a1 = *(const float4*)(&As[k][ty * 8 + 4]);
            float4 b0 = *(const float4*)(&Bs[k][tx * 8]);
            float4 b1 = *(const float4*)(&Bs[k][tx * 8 + 4]);
            float av8[8] = {a0.x, a0.y, a0.z, a0.w, a1.x, a1.y, a1.z, a1.w};
            float bv8[8] = {b0.x, b0.y, b0.z, b0.w, b1.x, b1.y, b1.z, b1.w};
            #pragma unroll
            for (int i = 0; i < 8; i++)
                #pragma unroll
                for (int j = 0; j < 8; j++)
                    acc[i][j] = fmaf(av8[i], bv8[j], acc[i][j]);
        }
        __syncthreads();
    }

    int row0 = bm + ty * 8;
    int col0 = bn + tx * 8;
    #pragma unroll
    for (int i = 0; i < 8; i++) {
        #pragma unroll
        for (int j = 0; j < 8; j++) {
            int n = col0 + j;
            if (n < N) {
                float v = acc[i][j];
                if (EPI == 1) {
                    v += extra[n];
                    // stable softplus: max(v,0) + log1p(exp(-|v|))
                    v = fmaxf(v, 0.f) + log1pf(__expf(-fabsf(v)));
                } else if (EPI == 2) {
                    v += extra[(size_t)(row0 + i) * N + n];
                }
                C[(size_t)(row0 + i) * N + n] = v;
            }
        }
    }
}

// ---------------- causal depthwise conv (K=4) + bias + silu ----------------
__global__ void __launch_bounds__(256) conv_silu_kernel(
    const float* __restrict__ proj, const float* __restrict__ cw,
    const float* __restrict__ cb, float* __restrict__ h)
{
    int idx = blockIdx.x * 256 + threadIdx.x;
    if (idx >= L_SEQ * DI) return;
    int d = idx & (DI - 1);
    int l = idx >> 12;            // / DI
    float s = cb[d];
    #pragma unroll
    for (int k = 0; k < KC; k++) {
        int ll = l - (KC - 1) + k;
        if (ll >= 0) s = fmaf(proj[(size_t)ll * (2 * DI) + d], cw[d * KC + k], s);
    }
    h[idx] = silu_f(s);
}

// ---------------- segment rmsnorm: dt[128] | B[16] | C[16] (one warp per row) ----------------
__global__ void __launch_bounds__(32) segnorm_kernel(
    const float* __restrict__ ssm,
    const float* __restrict__ wdt, const float* __restrict__ wb, const float* __restrict__ wc,
    float* __restrict__ dtn, float* __restrict__ Bn, float* __restrict__ Cn)
{
    int l = blockIdx.x;
    int lane = threadIdx.x;
    const float* row = ssm + (size_t)l * 160;

    // dt: 128 values, 4 per lane
    float v[4];
    float s = 0.f;
    #pragma unroll
    for (int i = 0; i < 4; i++) { v[i] = row[lane * 4 + i]; s += v[i] * v[i]; }
    #pragma unroll
    for (int o = 16; o >= 1; o >>= 1) s += __shfl_xor_sync(0xffffffffu, s, o);
    float r = rsqrtf(s / 128.f + 1e-6f);
    #pragma unroll
    for (int i = 0; i < 4; i++)
        dtn[(size_t)l * 128 + lane * 4 + i] = v[i] * r * wdt[lane * 4 + i];

    // B: 16 values on lanes 0..15
    float b = (lane < 16) ? row[128 + lane] : 0.f;
    float sb = b * b;
    #pragma unroll
    for (int o = 16; o >= 1; o >>= 1) sb += __shfl_xor_sync(0xffffffffu, sb, o);
    float rb = rsqrtf(sb / 16.f + 1e-6f);
    if (lane < 16) Bn[(size_t)l * 16 + lane] = b * rb * wb[lane];

    // C: 16 values
    float c = (lane < 16) ? row[144 + lane] : 0.f;
    float sc = c * c;
    #pragma unroll
    for (int o = 16; o >= 1; o >>= 1) sc += __shfl_xor_sync(0xffffffffu, sc, o);
    float rc = rsqrtf(sc / 16.f + 1e-6f);
    if (lane < 16) Cn[(size_t)l * 16 + lane] = c * rc * wc[lane];
}

// ---------------- selective scan: thread = (channel d, state n) ----------------
__global__ void __launch_bounds__(256) scan_kernel(
    const float* __restrict__ delta, const float* __restrict__ Bn,
    const float* __restrict__ Cn, const float* __restrict__ h,
    const float* __restrict__ proj, const float* __restrict__ Am,
    const float* __restrict__ Dv, float* __restrict__ y)
{
    int tid = blockIdx.x * 256 + threadIdx.x;   // 0 .. 65535
    int d = tid >> 4;
    int n = tid & 15;
    float a = Am[d * NS + n];
    float dval = Dv[d];
    float s = 0.f;
    for (int l = 0; l < L_SEQ; l++) {
        float dl = delta[(size_t)l * DI + d];
        float hl = h[(size_t)l * DI + d];
        float bl = Bn[(size_t)l * NS + n];
        float cl = Cn[(size_t)l * NS + n];
        float dA = __expf(dl * a);
        s = fmaf(dA, s, dl * bl * hl);
        float contrib = s * cl;
        contrib += __shfl_xor_sync(0xffffffffu, contrib, 1);
        contrib += __shfl_xor_sync(0xffffffffu, contrib, 2);
        contrib += __shfl_xor_sync(0xffffffffu, contrib, 4);
        contrib += __shfl_xor_sync(0xffffffffu, contrib, 8);
        if (n == 0) {
            float g = proj[(size_t)l * (2 * DI) + DI + d];
            y[(size_t)l * DI + d] = (contrib + hl * dval) * silu_f(g);
        }
    }
}

// ---------------- swiglu: act = silu(gu[:, :F]) * gu[:, F:] ----------------
__global__ void __launch_bounds__(256) swiglu_kernel(
    const float* __restrict__ gu, float* __restrict__ act)
{
    int idx = blockIdx.x * 256 + threadIdx.x;
    if (idx >= L_SEQ * FF) return;
    int l = idx >> 13;            // / FF
    int f = idx & (FF - 1);
    float g = gu[(size_t)l * (2 * FF) + f];
    float u = gu[(size_t)l * (2 * FF) + FF + f];
    act[idx] = silu_f(g) * u;
}

// ---------------- launch ----------------
extern "C" void kernel_launch(void* const* d_in, const int* in_sizes, int n_in,
                              void* d_out, int out_size)
{
    const float* hidden      = (const float*)d_in[0];
    const float* in_ln_w     = (const float*)d_in[1];
    const float* pre_ff_ln_w = (const float*)d_in[2];
    const float* in_proj_w   = (const float*)d_in[3];
    const float* conv_w      = (const float*)d_in[4];
    const float* conv_b      = (const float*)d_in[5];
    const float* x_proj_w    = (const float*)d_in[6];
    const float* dt_ln_w     = (const float*)d_in[7];
    const float* b_ln_w      = (const float*)d_in[8];
    const float* c_ln_w      = (const float*)d_in[9];
    const float* dt_proj_w   = (const float*)d_in[10];
    const float* dt_proj_b   = (const float*)d_in[11];
    const float* A           = (const float*)d_in[12];
    const float* Dv          = (const float*)d_in[13];
    const float* out_proj_w  = (const float*)d_in[14];
    const float* gate_up_w   = (const float*)d_in[15];
    const float* down_w      = (const float*)d_in[16];
    float* out = (float*)d_out;

    float *xn, *proj, *h, *ssm, *dtn, *Bn, *Cn, *delta, *y, *res2, *xn2, *gu, *act;
    cudaGetSymbolAddress((void**)&xn,    g_xn);
    cudaGetSymbolAddress((void**)&proj,  g_proj);
    cudaGetSymbolAddress((void**)&h,     g_h);
    cudaGetSymbolAddress((void**)&ssm,   g_ssm);
    cudaGetSymbolAddress((void**)&dtn,   g_dtn);
    cudaGetSymbolAddress((void**)&Bn,    g_Bn);
    cudaGetSymbolAddress((void**)&Cn,    g_Cn);
    cudaGetSymbolAddress((void**)&delta, g_delta);
    cudaGetSymbolAddress((void**)&y,     g_y);
    cudaGetSymbolAddress((void**)&res2,  g_res2);
    cudaGetSymbolAddress((void**)&xn2,   g_xn2);
    cudaGetSymbolAddress((void**)&gu,    g_gu);
    cudaGetSymbolAddress((void**)&act,   g_act);

    // 1. x = rmsnorm(hidden, in_ln_w)
    rmsnorm_kernel<<<L_SEQ, 256>>>(hidden, in_ln_w, xn, H_DIM);

    // 2. proj = x @ in_proj_w^T   [1024, 8192]
    gemm_abt<0><<<dim3((2 * DI) / 128, L_SEQ / 128), 256>>>(
        xn, in_proj_w, proj, L_SEQ, 2 * DI, H_DIM, nullptr);

    // 3. h = silu(causal_conv(proj[:, :Di]) + b)
    conv_silu_kernel<<<(L_SEQ * DI) / 256, 256>>>(proj, conv_w, conv_b, h);

    // 4. ssm = h @ x_proj_w^T   [1024, 160]
    gemm_abt<0><<<dim3(2, L_SEQ / 128), 256>>>(
        h, x_proj_w, ssm, L_SEQ, 160, DI, nullptr);

    // 5. segment rmsnorms
    segnorm_kernel<<<L_SEQ, 32>>>(ssm, dt_ln_w, b_ln_w, c_ln_w, dtn, Bn, Cn);

    // 6. delta = softplus(dtn @ dt_proj_w^T + dt_proj_b)   [1024, 4096]
    gemm_abt<1><<<dim3(DI / 128, L_SEQ / 128), 256>>>(
        dtn, dt_proj_w, delta, L_SEQ, DI, DT_R, dt_proj_b);

    // 7. selective scan + skip + gate  -> y [1024, 4096]
    scan_kernel<<<(DI * NS) / 256, 256>>>(delta, Bn, Cn, h, proj, A, Dv, y);

    // 8. res2 = hidden + y @ out_proj_w^T   [1024, 2048]
    gemm_abt<2><<<dim3(H_DIM / 128, L_SEQ / 128), 256>>>(
        y, out_proj_w, res2, L_SEQ, H_DIM, DI, hidden);

    // 9. x2 = rmsnorm(res2, pre_ff_ln_w)
    rmsnorm_kernel<<<L_SEQ, 256>>>(res2, pre_ff_ln_w, xn2, H_DIM);

    // 10. gu = x2 @ gate_up_w^T   [1024, 16384]
    gemm_abt<0><<<dim3((2 * FF) / 128, L_SEQ / 128), 256>>>(
        xn2, gate_up_w, gu, L_SEQ, 2 * FF, H_DIM, nullptr);

    // 11. act = silu(gu[:, :F]) * gu[:, F:]
    swiglu_kernel<<<(L_SEQ * FF) / 256, 256>>>(gu, act);

    // 12. out = res2 + act @ down_w^T   [1024, 2048]
    gemm_abt<2><<<dim3(H_DIM / 128, L_SEQ / 128), 256>>>(
        act, down_w, out, L_SEQ, H_DIM, FF, res2);
}

// round 3
// speedup vs baseline: 3.5814x; 3.5814x over previous
#include <cuda_runtime.h>
#include <cuda_fp16.h>
#include <math.h>
#include <stdint.h>

#define L_SEQ 1024
#define H_DIM 2048
#define DI    4096
#define DT_R  128
#define NS    16
#define KC    4
#define FF    8192

// ---------------- scratch (static device globals; no allocation) ----------------
__device__ float g_proj [L_SEQ * 2 * DI];
__device__ float g_h    [L_SEQ * DI];
__device__ float g_ssm  [L_SEQ * 160];
__device__ float g_Bn   [L_SEQ * NS];
__device__ float g_Cn   [L_SEQ * NS];
__device__ float g_delta[L_SEQ * DI];
__device__ float g_res2 [L_SEQ * H_DIM];
__device__ float g_gu   [L_SEQ * 2 * FF];
// fp16 activations
__device__ __half g_xnh  [L_SEQ * H_DIM];
__device__ __half g_hh   [L_SEQ * DI];
__device__ __half g_dtnh [L_SEQ * DT_R];
__device__ __half g_yh   [L_SEQ * DI];
__device__ __half g_xn2h [L_SEQ * H_DIM];
__device__ __half g_acth [L_SEQ * FF];
// fp16 weights
__device__ __half g_w_in [2 * DI * H_DIM];
__device__ __half g_w_x  [160 * DI];
__device__ __half g_w_dt [DI * DT_R];
__device__ __half g_w_out[H_DIM * DI];
__device__ __half g_w_gu [2 * FF * H_DIM];
__device__ __half g_w_dn [H_DIM * FF];

// ================= PTX helpers (sm_103 baseline ISA only) =================
__device__ __forceinline__ uint32_t smem_u32(const void* p) {
    uint32_t a;
    asm("{ .reg .u64 t; cvta.to.shared.u64 t, %1; cvt.u32.u64 %0, t; }" : "=r"(a) : "l"(p));
    return a;
}
__device__ __forceinline__ void cp16(uint32_t dst, const void* src, int sz) {
    asm volatile("cp.async.cg.shared.global [%0], [%1], 16, %2;"
                 :: "r"(dst), "l"(src), "r"(sz));
}
__device__ __forceinline__ void cp_commit() {
    asm volatile("cp.async.commit_group;" ::: "memory");
}
__device__ __forceinline__ void cp_wait0() {
    asm volatile("cp.async.wait_group 0;" ::: "memory");
}
__device__ __forceinline__ void ldsm4(uint32_t& r0, uint32_t& r1, uint32_t& r2, uint32_t& r3, uint32_t a) {
    asm volatile("ldmatrix.sync.aligned.m8n8.x4.shared.b16 {%0,%1,%2,%3}, [%4];"
                 : "=r"(r0), "=r"(r1), "=r"(r2), "=r"(r3) : "r"(a));
}
__device__ __forceinline__ void ldsm2(uint32_t& r0, uint32_t& r1, uint32_t a) {
    asm volatile("ldmatrix.sync.aligned.m8n8.x2.shared.b16 {%0,%1}, [%2];"
                 : "=r"(r0), "=r"(r1) : "r"(a));
}
__device__ __forceinline__ void mma16816(float* c, const uint32_t* a, const uint32_t* b) {
    asm volatile("mma.sync.aligned.m16n8k16.row.col.f32.f16.f16.f32 "
                 "{%0,%1,%2,%3}, {%4,%5,%6,%7}, {%8,%9}, {%0,%1,%2,%3};"
                 : "+f"(c[0]), "+f"(c[1]), "+f"(c[2]), "+f"(c[3])
                 : "r"(a[0]), "r"(a[1]), "r"(a[2]), "r"(a[3]), "r"(b[0]), "r"(b[1]));
}

__device__ __forceinline__ float silu_f(float x) { return x / (1.f + __expf(-x)); }

// ================= fp32 -> fp16 convert =================
__global__ void __launch_bounds__(256) f2h_kernel(const float4* __restrict__ s,
                                                  uint2* __restrict__ d, int n4) {
    int i = blockIdx.x * 256 + threadIdx.x;
    if (i >= n4) return;
    float4 v = s[i];
    __half2 a = __floats2half2_rn(v.x, v.y);
    __half2 b = __floats2half2_rn(v.z, v.w);
    uint2 o;
    o.x = *reinterpret_cast<uint32_t*>(&a);
    o.y = *reinterpret_cast<uint32_t*>(&b);
    d[i] = o;
}

// ================= rmsnorm (fp32 in, fp16 out) =================
__global__ void __launch_bounds__(256) rmsnorm_kernel(
    const float* __restrict__ x, const float* __restrict__ w,
    __half* __restrict__ out, int D)
{
    int row = blockIdx.x;
    const float* xr = x + (size_t)row * D;
    float s = 0.f;
    for (int i = threadIdx.x; i < D; i += 256) { float v = xr[i]; s += v * v; }
    __shared__ float red[8];
    #pragma unroll
    for (int o = 16; o >= 1; o >>= 1) s += __shfl_xor_sync(0xffffffffu, s, o);
    int warp = threadIdx.x >> 5;
    if ((threadIdx.x & 31) == 0) red[warp] = s;
    __syncthreads();
    if (warp == 0) {
        float t = ((threadIdx.x & 31) < 8) ? red[threadIdx.x & 31] : 0.f;
        #pragma unroll
        for (int o = 4; o >= 1; o >>= 1) t += __shfl_xor_sync(0xffffffffu, t, o);
        if (threadIdx.x == 0) red[0] = t;
    }
    __syncthreads();
    float r = rsqrtf(red[0] / (float)D + 1e-6f);
    __half* orow = out + (size_t)row * D;
    for (int i = threadIdx.x; i < D; i += 256)
        orow[i] = __float2half(xr[i] * r * w[i]);
}

// ================= HMMA GEMM: C[M,N] = A[M,K] @ B[N,K]^T =================
// 128x128x32 tile, 8 warps (2x4), warp tile 64x32, m16n8k16 mma.
// EPI 0: plain   EPI 1: +bias[n], softplus   EPI 2: +extra[m*N+n]
template <int EPI>
__global__ void __launch_bounds__(256) hgemm(
    const __half* __restrict__ A, const __half* __restrict__ B,
    float* __restrict__ C, int M, int N, int K,
    const float* __restrict__ extra)
{
    __shared__ __align__(16) __half As[2][128][40];   // 40-half stride: conflict-free ldmatrix
    __shared__ __align__(16) __half Bs[2][128][40];

    const int tid = threadIdx.x;
    const int lane = tid & 31;
    const int wid = tid >> 5;
    const int wm = wid >> 2;       // 0..1
    const int wn = wid & 3;        // 0..3
    const int bm = blockIdx.y * 128;
    const int bn = blockIdx.x * 128;

    const uint32_t sA = smem_u32(As);
    const uint32_t sB = smem_u32(Bs);
    const uint32_t ABUF = 128 * 40 * 2;   // bytes per buffer

    float c[4][4][4];
    #pragma unroll
    for (int i = 0; i < 4; i++)
        #pragma unroll
        for (int j = 0; j < 4; j++)
            #pragma unroll
            for (int k = 0; k < 4; k++) c[i][j][k] = 0.f;

    // tile loader: 128 rows x 32 halves (64B/row), 4 x 16B chunks per row
    const int lrow = tid >> 2;          // 0..63 (+64 on second iter)
    const int lq   = (tid & 3) * 8;     // half offset within row

    auto load_tile = [&](int t, int buf) {
        int k0 = t * 32;
        #pragma unroll
        for (int i = 0; i < 2; i++) {
            int row = lrow + i * 64;
            cp16(sA + buf * ABUF + (row * 40 + lq) * 2,
                 A + (size_t)(bm + row) * K + k0 + lq, 16);
        }
        #pragma unroll
        for (int i = 0; i < 2; i++) {
            int row = lrow + i * 64;
            int gr = bn + row;
            const __half* src = B + (size_t)(gr < N ? gr : 0) * K + k0 + lq;
            cp16(sB + buf * ABUF + (row * 40 + lq) * 2, src, gr < N ? 16 : 0);
        }
        cp_commit();
    };

    load_tile(0, 0);
    const int nt = K >> 5;

    for (int t = 0; t < nt; t++) {
        cp_wait0();
        __syncthreads();
        if (t + 1 < nt) load_tile(t + 1, (t + 1) & 1);

        const uint32_t aBase = sA + (t & 1) * ABUF;
        const uint32_t bBase = sB + (t & 1) * ABUF;
        #pragma unroll
        for (int ks = 0; ks < 2; ks++) {
            uint32_t a[4][4];
            #pragma unroll
            for (int mf = 0; mf < 4; mf++) {
                int row = wm * 64 + mf * 16 + (lane & 15);
                int col = ks * 16 + (lane >> 4) * 8;
                ldsm4(a[mf][0], a[mf][1], a[mf][2], a[mf][3],
                      aBase + (row * 40 + col) * 2);
            }
            uint32_t b[4][2];
            #pragma unroll
            for (int nf = 0; nf < 4; nf++) {
                int row = wn * 32 + nf * 8 + (lane & 7);
                int col = ks * 16 + ((lane >> 3) & 1) * 8;
                ldsm2(b[nf][0], b[nf][1], bBase + (row * 40 + col) * 2);
            }
            #pragma unroll
            for (int mf = 0; mf < 4; mf++)
                #pragma unroll
                for (int nf = 0; nf < 4; nf++)
                    mma16816(c[mf][nf], a[mf], b[nf]);
        }
        __syncthreads();
    }

    // epilogue: direct fp32 stores (float2 per lane-fragment)
    #pragma unroll
    for (int mf = 0; mf < 4; mf++) {
        #pragma unroll
        for (int nf = 0; nf < 4; nf++) {
            int m0 = bm + wm * 64 + mf * 16 + (lane >> 2);
            int n0 = bn + wn * 32 + nf * 8 + (lane & 3) * 2;
            if (n0 < N) {       // N is even; pair always in-bounds together
                #pragma unroll
                for (int hh = 0; hh < 2; hh++) {
                    int m = m0 + hh * 8;
                    float v0 = c[mf][nf][hh * 2 + 0];
                    float v1 = c[mf][nf][hh * 2 + 1];
                    if (EPI == 1) {
                        v0 += extra[n0];
                        v1 += extra[n0 + 1];
                        v0 = fmaxf(v0, 0.f) + log1pf(__expf(-fabsf(v0)));
                        v1 = fmaxf(v1, 0.f) + log1pf(__expf(-fabsf(v1)));
                    } else if (EPI == 2) {
                        v0 += extra[(size_t)m * N + n0];
                        v1 += extra[(size_t)m * N + n0 + 1];
                    }
                    *(float2*)(C + (size_t)m * N + n0) = make_float2(v0, v1);
                }
            }
        }
    }
}

// ================= causal depthwise conv + bias + silu =================
__global__ void __launch_bounds__(256) conv_silu_kernel(
    const float* __restrict__ proj, const float* __restrict__ cw,
    const float* __restrict__ cb, float* __restrict__ h, __half* __restrict__ hh)
{
    int idx = blockIdx.x * 256 + threadIdx.x;
    if (idx >= L_SEQ * DI) return;
    int d = idx & (DI - 1);
    int l = idx >> 12;
    float s = cb[d];
    #pragma unroll
    for (int k = 0; k < KC; k++) {
        int ll = l - (KC - 1) + k;
        if (ll >= 0) s = fmaf(proj[(size_t)ll * (2 * DI) + d], cw[d * KC + k], s);
    }
    float v = silu_f(s);
    h[idx] = v;
    hh[idx] = __float2half(v);
}

// ================= segment rmsnorm: dt[128] | B[16] | C[16] =================
__global__ void __launch_bounds__(32) segnorm_kernel(
    const float* __restrict__ ssm,
    const float* __restrict__ wdt, const float* __restrict__ wb, const float* __restrict__ wc,
    __half* __restrict__ dtnh, float* __restrict__ Bn, float* __restrict__ Cn)
{
    int l = blockIdx.x;
    int lane = threadIdx.x;
    const float* row = ssm + (size_t)l * 160;

    float v[4];
    float s = 0.f;
    #pragma unroll
    for (int i = 0; i < 4; i++) { v[i] = row[lane * 4 + i]; s += v[i] * v[i]; }
    #pragma unroll
    for (int o = 16; o >= 1; o >>= 1) s += __shfl_xor_sync(0xffffffffu, s, o);
    float r = rsqrtf(s / 128.f + 1e-6f);
    #pragma unroll
    for (int i = 0; i < 4; i++)
        dtnh[(size_t)l * 128 + lane * 4 + i] = __float2half(v[i] * r * wdt[lane * 4 + i]);

    float b = (lane < 16) ? row[128 + lane] : 0.f;
    float sb = b * b;
    #pragma unroll
    for (int o = 16; o >= 1; o >>= 1) sb += __shfl_xor_sync(0xffffffffu, sb, o);
    float rb = rsqrtf(sb / 16.f + 1e-6f);
    if (lane < 16) Bn[(size_t)l * 16 + lane] = b * rb * wb[lane];

    float c = (lane < 16) ? row[144 + lane] : 0.f;
    float sc = c * c;
    #pragma unroll
    for (int o = 16; o >= 1; o >>= 1) sc += __shfl_xor_sync(0xffffffffu, sc, o);
    float rc = rsqrtf(sc / 16.f + 1e-6f);
    if (lane < 16) Cn[(size_t)l * 16 + lane] = c * rc * wc[lane];
}

// ================= selective scan =================
__global__ void __launch_bounds__(256) scan_kernel(
    const float* __restrict__ delta, const float* __restrict__ Bn,
    const float* __restrict__ Cn, const float* __restrict__ h,
    const float* __restrict__ proj, const float* __restrict__ Am,
    const float* __restrict__ Dv, __half* __restrict__ yh)
{
    int tid = blockIdx.x * 256 + threadIdx.x;
    int d = tid >> 4;
    int n = tid & 15;
    float a = Am[d * NS + n];
    float dval = Dv[d];
    float s = 0.f;
    for (int l = 0; l < L_SEQ; l++) {
        float dl = delta[(size_t)l * DI + d];
        float hl = h[(size_t)l * DI + d];
        float bl = Bn[(size_t)l * NS + n];
        float cl = Cn[(size_t)l * NS + n];
        float dA = __expf(dl * a);
        s = fmaf(dA, s, dl * bl * hl);
        float contrib = s * cl;
        contrib += __shfl_xor_sync(0xffffffffu, contrib, 1);
        contrib += __shfl_xor_sync(0xffffffffu, contrib, 2);
        contrib += __shfl_xor_sync(0xffffffffu, contrib, 4);
        contrib += __shfl_xor_sync(0xffffffffu, contrib, 8);
        if (n == 0) {
            float g = proj[(size_t)l * (2 * DI) + DI + d];
            yh[(size_t)l * DI + d] = __float2half((contrib + hl * dval) * silu_f(g));
        }
    }
}

// ================= swiglu =================
__global__ void __launch_bounds__(256) swiglu_kernel(
    const float* __restrict__ gu, __half* __restrict__ acth)
{
    int idx = blockIdx.x * 256 + threadIdx.x;
    if (idx >= L_SEQ * FF) return;
    int l = idx >> 13;
    int f = idx & (FF - 1);
    float g = gu[(size_t)l * (2 * FF) + f];
    float u = gu[(size_t)l * (2 * FF) + FF + f];
    acth[idx] = __float2half(silu_f(g) * u);
}

// ================= launch =================
extern "C" void kernel_launch(void* const* d_in, const int* in_sizes, int n_in,
                              void* d_out, int out_size)
{
    const float* hidden      = (const float*)d_in[0];
    const float* in_ln_w     = (const float*)d_in[1];
    const float* pre_ff_ln_w = (const float*)d_in[2];
    const float* in_proj_w   = (const float*)d_in[3];
    const float* conv_w      = (const float*)d_in[4];
    const float* conv_b      = (const float*)d_in[5];
    const float* x_proj_w    = (const float*)d_in[6];
    const float* dt_ln_w     = (const float*)d_in[7];
    const float* b_ln_w      = (const float*)d_in[8];
    const float* c_ln_w      = (const float*)d_in[9];
    const float* dt_proj_w   = (const float*)d_in[10];
    const float* dt_proj_b   = (const float*)d_in[11];
    const float* A           = (const float*)d_in[12];
    const float* Dv          = (const float*)d_in[13];
    const float* out_proj_w  = (const float*)d_in[14];
    const float* gate_up_w   = (const float*)d_in[15];
    const float* down_w      = (const float*)d_in[16];
    float* out = (float*)d_out;

    float *proj, *h, *ssm, *Bn, *Cn, *delta, *res2, *gu;
    __half *xnh, *hh, *dtnh, *yh, *xn2h, *acth;
    __half *w_in, *w_x, *w_dt, *w_out, *w_gu, *w_dn;
    cudaGetSymbolAddress((void**)&proj,  g_proj);
    cudaGetSymbolAddress((void**)&h,     g_h);
    cudaGetSymbolAddress((void**)&ssm,   g_ssm);
    cudaGetSymbolAddress((void**)&Bn,    g_Bn);
    cudaGetSymbolAddress((void**)&Cn,    g_Cn);
    cudaGetSymbolAddress((void**)&delta, g_delta);
    cudaGetSymbolAddress((void**)&res2,  g_res2);
    cudaGetSymbolAddress((void**)&gu,    g_gu);
    cudaGetSymbolAddress((void**)&xnh,   g_xnh);
    cudaGetSymbolAddress((void**)&hh,    g_hh);
    cudaGetSymbolAddress((void**)&dtnh,  g_dtnh);
    cudaGetSymbolAddress((void**)&yh,    g_yh);
    cudaGetSymbolAddress((void**)&xn2h,  g_xn2h);
    cudaGetSymbolAddress((void**)&acth,  g_acth);
    cudaGetSymbolAddress((void**)&w_in,  g_w_in);
    cudaGetSymbolAddress((void**)&w_x,   g_w_x);
    cudaGetSymbolAddress((void**)&w_dt,  g_w_dt);
    cudaGetSymbolAddress((void**)&w_out, g_w_out);
    cudaGetSymbolAddress((void**)&w_gu,  g_w_gu);
    cudaGetSymbolAddress((void**)&w_dn,  g_w_dn);

    // weight fp32 -> fp16 conversions
    auto cvt = [](const float* s, __half* d, int n) {
        int n4 = n / 4;
        f2h_kernel<<<(n4 + 255) / 256, 256>>>((const float4*)s, (uint2*)d, n4);
    };
    cvt(in_proj_w,  w_in,  2 * DI * H_DIM);
    cvt(x_proj_w,   w_x,   160 * DI);
    cvt(dt_proj_w,  w_dt,  DI * DT_R);
    cvt(out_proj_w, w_out, H_DIM * DI);
    cvt(gate_up_w,  w_gu,  2 * FF * H_DIM);
    cvt(down_w,     w_dn,  H_DIM * FF);

    // 1. xn = rmsnorm(hidden) -> fp16
    rmsnorm_kernel<<<L_SEQ, 256>>>(hidden, in_ln_w, xnh, H_DIM);

    // 2. proj = xn @ in_proj_w^T   [1024, 8192], K=2048
    hgemm<0><<<dim3((2 * DI) / 128, L_SEQ / 128), 256>>>(
        xnh, w_in, proj, L_SEQ, 2 * DI, H_DIM, nullptr);

    // 3. h = silu(conv(proj[:, :Di]) + b)
    conv_silu_kernel<<<(L_SEQ * DI) / 256, 256>>>(proj, conv_w, conv_b, h, hh);

    // 4. ssm = h @ x_proj_w^T   [1024, 160], K=4096
    hgemm<0><<<dim3(2, L_SEQ / 128), 256>>>(
        hh, w_x, ssm, L_SEQ, 160, DI, nullptr);

    // 5. segment rmsnorms
    segnorm_kernel<<<L_SEQ, 32>>>(ssm, dt_ln_w, b_ln_w, c_ln_w, dtnh, Bn, Cn);

    // 6. delta = softplus(dtn @ dt_proj_w^T + b)   [1024, 4096], K=128
    hgemm<1><<<dim3(DI / 128, L_SEQ / 128), 256>>>(
        dtnh, w_dt, delta, L_SEQ, DI, DT_R, dt_proj_b);

    // 7. selective scan + skip + gate
    scan_kernel<<<(DI * NS) / 256, 256>>>(delta, Bn, Cn, h, proj, A, Dv, yh);

    // 8. res2 = hidden + y @ out_proj_w^T   [1024, 2048], K=4096
    hgemm<2><<<dim3(H_DIM / 128, L_SEQ / 128), 256>>>(
        yh, w_out, res2, L_SEQ, H_DIM, DI, hidden);

    // 9. xn2 = rmsnorm(res2) -> fp16
    rmsnorm_kernel<<<L_SEQ, 256>>>(res2, pre_ff_ln_w, xn2h, H_DIM);

    // 10. gu = xn2 @ gate_up_w^T   [1024, 16384], K=2048
    hgemm<0><<<dim3((2 * FF) / 128, L_SEQ / 128), 256>>>(
        xn2h, w_gu, gu, L_SEQ, 2 * FF, H_DIM, nullptr);

    // 11. act = silu(gu[:, :F]) * gu[:, F:]
    swiglu_kernel<<<(L_SEQ * FF) / 256, 256>>>(gu, acth);

    // 12. out = res2 + act @ down_w^T   [1024, 2048], K=8192
    hgemm<2><<<dim3(H_DIM / 128, L_SEQ / 128), 256>>>(
        acth, w_dn, out, L_SEQ, H_DIM, FF, res2);
}